// round 14
// baseline (speedup 1.0000x reference)
#include <cuda_runtime.h>
#include <cuda_fp16.h>
#include <cstdint>

// Problem constants
#define BB  2
#define SS  2048
#define DDm 1024
#define HH  16
#define DK  64
#define MT  (BB*SS)      // 4096

// Scratch (allocation-free: __device__ globals), all fp16
__device__ __half g_Qh[BB*HH*SS*DK];
__device__ __half g_Kh[BB*HH*SS*DK];
__device__ __half g_Vh[BB*HH*SS*DK];
__device__ __half g_Ah[MT*DDm];        // attn ctx (O-proj input)
__device__ __half g_Xqh[MT*DDm];
__device__ __half g_Xkh[MT*DDm];
__device__ __half g_Xvh[MT*DDm];
__device__ __half g_Wqh[DDm*DDm];
__device__ __half g_Wkh[DDm*DDm];
__device__ __half g_Wvh[DDm*DDm];
__device__ __half g_Woh[DDm*DDm];

// ---------------------------------------------------------------------------
// helpers
// ---------------------------------------------------------------------------
__device__ __forceinline__ uint32_t smem_u32(const void* p) {
    uint32_t a;
    asm("{ .reg .u64 t; cvta.to.shared.u64 t, %1; cvt.u32.u64 %0, t; }"
        : "=r"(a) : "l"(p));
    return a;
}
__device__ __forceinline__ void cp16(uint32_t saddr, const void* gaddr) {
    asm volatile("cp.async.cg.shared.global [%0], [%1], 16;"
                 :: "r"(saddr), "l"(gaddr));
}
__device__ __forceinline__ void ldsm4(uint32_t* r, uint32_t addr) {
    asm volatile("ldmatrix.sync.aligned.m8n8.x4.shared.b16 {%0,%1,%2,%3}, [%4];"
                 : "=r"(r[0]), "=r"(r[1]), "=r"(r[2]), "=r"(r[3]) : "r"(addr));
}
__device__ __forceinline__ void ldsm4t(uint32_t* r, uint32_t addr) {
    asm volatile("ldmatrix.sync.aligned.m8n8.x4.trans.shared.b16 {%0,%1,%2,%3}, [%4];"
                 : "=r"(r[0]), "=r"(r[1]), "=r"(r[2]), "=r"(r[3]) : "r"(addr));
}
__device__ __forceinline__ void mma_f16(float* c, const uint32_t* a,
                                        const uint32_t* b) {
    asm volatile(
        "mma.sync.aligned.m16n8k16.row.col.f32.f16.f16.f32 "
        "{%0,%1,%2,%3}, {%4,%5,%6,%7}, {%8,%9}, {%0,%1,%2,%3};"
        : "+f"(c[0]), "+f"(c[1]), "+f"(c[2]), "+f"(c[3])
        : "r"(a[0]), "r"(a[1]), "r"(a[2]), "r"(a[3]), "r"(b[0]), "r"(b[1]));
}
__device__ __forceinline__ float ex2(float x) {
    float r;
    asm("ex2.approx.f32 %0, %1;" : "=f"(r) : "f"(x));
    return r;
}

// ---------------------------------------------------------------------------
// fused fp32 -> fp16 convert: 7 segments in ONE launch
// ---------------------------------------------------------------------------
__global__ void __launch_bounds__(256) split_all(
    const float4* __restrict__ x0, const float4* __restrict__ x1,
    const float4* __restrict__ x2, const float4* __restrict__ x3,
    const float4* __restrict__ x4, const float4* __restrict__ x5,
    const float4* __restrict__ x6,
    __half2* __restrict__ h0, __half2* __restrict__ h1,
    __half2* __restrict__ h2, __half2* __restrict__ h3,
    __half2* __restrict__ h4, __half2* __restrict__ h5,
    __half2* __restrict__ h6,
    int n4w, int bpw, int n4a, int bpa)
{
    int seg, bid, n4;
    const int bx = blockIdx.x;
    if (bx < 4 * bpw) { seg = bx / bpw;       bid = bx % bpw;       n4 = n4w; }
    else              { const int r = bx - 4 * bpw;
                        seg = 4 + r / bpa;    bid = r % bpa;        n4 = n4a; }

    const float4* x;
    __half2* hi;
    switch (seg) {
        case 0: x = x0; hi = h0; break;
        case 1: x = x1; hi = h1; break;
        case 2: x = x2; hi = h2; break;
        case 3: x = x3; hi = h3; break;
        case 4: x = x4; hi = h4; break;
        case 5: x = x5; hi = h5; break;
        default: x = x6; hi = h6; break;
    }

    const int i = bid * blockDim.x + threadIdx.x;
    if (i >= n4) return;
    float4 v = x[i];
    hi[2*i]   = __halves2half2(__float2half_rn(v.x), __float2half_rn(v.y));
    hi[2*i+1] = __halves2half2(__float2half_rn(v.z), __float2half_rn(v.w));
}

// ---------------------------------------------------------------------------
// HMMA GEMM body (1-product fp16): C = A@W^T + bias, scaled by oscale.
// ONE WARP per CTA, tile 64x64, BK=32, 2-stage double buffer.
// Fine CTA grain minimizes per-SM work quantization.
// MODE 1: write fp32 plain [M,N] (C);  MODE 2: write fp16 split-head (Ch)
// ---------------------------------------------------------------------------
#define T64_B    5120               // 64 rows * 80 B
#define STAGE_B  (2 * T64_B)        // A, W: 10240
#define GEMM_SMEM (2 * STAGE_B)     // 20480 (2 stages)

template<int MODE>
__device__ __forceinline__ void gemm_body(
    const __half* __restrict__ Ah, const __half* __restrict__ Wh,
    const float* __restrict__ bias, float* __restrict__ C,
    __half* __restrict__ Ch, float oscale, int M, int N, int K, char* smem)
{
    const uint32_t sbase = smem_u32(smem);

    const int lane = threadIdx.x;     // 0..31, single warp
    const int m0   = blockIdx.y * 64;
    const int n0   = blockIdx.x * 64;

    float acc[4][8][4];
#pragma unroll
    for (int i = 0; i < 4; i++)
#pragma unroll
        for (int j = 0; j < 8; j++)
#pragma unroll
            for (int r = 0; r < 4; r++) acc[i][j][r] = 0.0f;

    auto load_chunk = [&](int i, int buf) {
        const int kc0 = i * 32;
        const uint32_t stage = sbase + (uint32_t)buf * STAGE_B;
#pragma unroll
        for (int t = 0; t < 2; t++) {
            const __half* src = (t == 0) ? Ah : Wh;
            const int r0 = (t == 0) ? m0 : n0;
#pragma unroll
            for (int h = 0; h < 8; h++) {
                const int idx = lane + h * 32;
                const int row = idx >> 2, c = idx & 3;
                cp16(stage + t * T64_B + row * 80 + c * 16,
                     src + (size_t)(r0 + row) * K + kc0 + c * 8);
            }
        }
    };

    const int mid = lane >> 3;
    const int lr  = lane & 7;
    const int a_moff = (mid & 1) * 8;
    const int a_koff = (mid >> 1) * 8;
    const int b_noff = (mid >> 1) * 8;
    const int b_koff = (mid & 1) * 8;

    const int NCH = K / 32;

    load_chunk(0, 0);
    asm volatile("cp.async.commit_group;" ::: "memory");

    for (int i = 0; i < NCH; i++) {
        if (i + 1 < NCH) {
            load_chunk(i + 1, (i + 1) & 1);
            asm volatile("cp.async.commit_group;" ::: "memory");
            asm volatile("cp.async.wait_group 1;" ::: "memory");
        } else {
            asm volatile("cp.async.wait_group 0;" ::: "memory");
        }
        __syncwarp();

        const uint32_t stage = sbase + (uint32_t)(i & 1) * STAGE_B;
        const uint32_t tAh = stage;
        const uint32_t tWh = stage + T64_B;

#pragma unroll
        for (int ks = 0; ks < 2; ks++) {
            uint32_t ah[4][4], bh[8][2];
#pragma unroll
            for (int mt = 0; mt < 4; mt++) {
                const int r  = mt * 16 + a_moff + lr;
                const int kc = ks * 16 + a_koff;
                ldsm4(ah[mt], tAh + r * 80 + kc * 2);
            }
#pragma unroll
            for (int np = 0; np < 4; np++) {
                const int r  = np * 16 + b_noff + lr;
                const int kc = ks * 16 + b_koff;
                uint32_t t4r[4];
                ldsm4(t4r, tWh + r * 80 + kc * 2);
                bh[2*np][0] = t4r[0]; bh[2*np][1] = t4r[1];
                bh[2*np+1][0] = t4r[2]; bh[2*np+1][1] = t4r[3];
            }
#pragma unroll
            for (int mt = 0; mt < 4; mt++)
#pragma unroll
                for (int nt = 0; nt < 8; nt++)
                    mma_f16(acc[mt][nt], ah[mt], bh[nt]);
        }
        __syncwarp();
    }

    const int g  = lane >> 2;
    const int t4 = lane & 3;
#pragma unroll
    for (int mt = 0; mt < 4; mt++) {
#pragma unroll
        for (int nt = 0; nt < 8; nt++) {
            const int col = n0 + nt * 8 + t4 * 2;
            const float bx = bias[col], by = bias[col + 1];
#pragma unroll
            for (int half = 0; half < 2; half++) {
                const int row = m0 + mt * 16 + g + half * 8;
                const float v0 = (acc[mt][nt][half * 2 + 0] + bx) * oscale;
                const float v1 = (acc[mt][nt][half * 2 + 1] + by) * oscale;
                if (MODE == 2) {
                    const int bi = row >> 11;
                    const int s  = row & (SS - 1);
                    const int h  = col >> 6;
                    const int dk = col & 63;
                    const size_t idx = (((size_t)(bi * HH + h) * SS + s) * DK + dk);
                    *(__half2*)(Ch + idx) = __halves2half2(
                        __float2half_rn(v0), __float2half_rn(v1));
                } else {
                    float* dst = C + (size_t)row * N + col;
                    *(float2*)dst = make_float2(v0, v1);
                }
            }
        }
    }
}

// fused Q/K/V projection: blockIdx.z selects (input, weight, bias, output)
__global__ void __launch_bounds__(32) gemm_qkv(
    const __half* __restrict__ Aq, const __half* __restrict__ Ak,
    const __half* __restrict__ Av,
    const __half* __restrict__ Wq, const __half* __restrict__ Wk,
    const __half* __restrict__ Wv,
    const float* __restrict__ bq, const float* __restrict__ bk,
    const float* __restrict__ bv,
    __half* __restrict__ Cq, __half* __restrict__ Ck, __half* __restrict__ Cv,
    float csq, int M, int N, int K)
{
    extern __shared__ __align__(16) char smem[];
    const int z = blockIdx.z;
    const __half* A = (z == 0) ? Aq : (z == 1) ? Ak : Av;
    const __half* W = (z == 0) ? Wq : (z == 1) ? Wk : Wv;
    const float*  b = (z == 0) ? bq : (z == 1) ? bk : bv;
    __half*       Cc = (z == 0) ? Cq : (z == 1) ? Ck : Cv;
    const float  os = (z == 0) ? csq : 1.0f;
    gemm_body<2>(A, W, b, nullptr, Cc, os, M, N, K, smem);
}

// O projection (fp32 output)
__global__ void __launch_bounds__(32) gemm_o(
    const __half* __restrict__ A, const __half* __restrict__ W,
    const float* __restrict__ bias, float* __restrict__ C,
    int M, int N, int K)
{
    extern __shared__ __align__(16) char smem[];
    gemm_body<1>(A, W, bias, C, nullptr, 1.0f, M, N, K, smem);
}

// ---------------------------------------------------------------------------
// Flash attention via fp16 HMMA, all single-product (unchanged).
// ---------------------------------------------------------------------------
#define P144 144
#define KV_T   (64 * P144)              // one tensor tile: 9216 B
#define KV_ST  (2 * KV_T)               // K, V: 18432 B
#define Q_BYTES (128 * P144)            // 18432 B
#define ATT_SMEM (Q_BYTES + 2 * KV_ST)  // 55296

__global__ void __launch_bounds__(256) attn_mma(
    const __half* __restrict__ Q_, const __half* __restrict__ K_,
    const __half* __restrict__ V_, __half* __restrict__ Ch)
{
    extern __shared__ __align__(16) char smem[];
    const uint32_t sb = smem_u32(smem);

    const int qt = (int)gridDim.x - 1 - (int)blockIdx.x;  // heavy tiles first
    const int h = blockIdx.y, b = blockIdx.z;
    const int q0 = qt * 128;
    const size_t bh = ((size_t)b * HH + h) * SS * DK;

    const int tid  = threadIdx.x;
    const int lane = tid & 31;
    const int wid  = tid >> 5;
    const int wr0  = wid * 16;
    const int g    = lane >> 2;
    const int t4   = lane & 3;
    const int mid  = lane >> 3;
    const int lr   = lane & 7;

    const int nkt = 2 * (qt + 1);

    auto load_kv = [&](int kt, int buf) {
        const uint32_t stage = sb + Q_BYTES + (uint32_t)buf * KV_ST;
        const size_t go = bh + (size_t)kt * 64 * DK;
        const __half* srcs[2] = {K_ + go, V_ + go};
#pragma unroll
        for (int t = 0; t < 2; t++) {
#pragma unroll
            for (int j = 0; j < 2; j++) {
                const int idx = tid + j * 256;
                const int r = idx >> 3, s = idx & 7;
                cp16(stage + t * KV_T + r * P144 + s * 16, srcs[t] + r * 64 + s * 8);
            }
        }
    };

    load_kv(0, 0);
    asm volatile("cp.async.commit_group;" ::: "memory");

    // stage Q (128 x 64 fp16)
    {
        const __half* sq = Q_ + bh + (size_t)q0 * DK;
#pragma unroll
        for (int j = 0; j < 4; j++) {
            const int idx = tid + j * 256;
            const int r = idx >> 3, s = idx & 7;
            *(uint4*)(smem + r * P144 + s * 16) = *(const uint4*)(sq + r * 64 + s * 8);
        }
    }
    __syncthreads();

    const uint32_t aoff = (uint32_t)((wr0 + (mid & 1) * 8 + lr) * P144) + (mid >> 1) * 16;
    uint32_t qh[4][4];
#pragma unroll
    for (int kc = 0; kc < 4; kc++)
        ldsm4(qh[kc], sb + aoff + kc * 32);

    float m0 = -1e30f, m1 = -1e30f, l0 = 0.0f, l1 = 0.0f;
    float O[8][4];
#pragma unroll
    for (int d = 0; d < 8; d++)
#pragma unroll
        for (int e = 0; e < 4; e++) O[d][e] = 0.0f;

    const uint32_t boff = (uint32_t)(((mid >> 1) * 8 + lr) * P144) + (mid & 1) * 16;

    for (int kt = 0; kt < nkt; kt++) {
        if (kt + 1 < nkt) {
            load_kv(kt + 1, (kt + 1) & 1);
            asm volatile("cp.async.commit_group;" ::: "memory");
            asm volatile("cp.async.wait_group 1;" ::: "memory");
        } else {
            asm volatile("cp.async.wait_group 0;" ::: "memory");
        }
        __syncthreads();

        if (kt * 64 <= q0 + wr0 + 15) {
            const uint32_t stage = sb + Q_BYTES + (uint32_t)(kt & 1) * KV_ST;
            const uint32_t sK = stage, sV = stage + KV_T;

            float S[8][4];
#pragma unroll
            for (int nt = 0; nt < 8; nt++)
#pragma unroll
                for (int e = 0; e < 4; e++) S[nt][e] = 0.0f;

            // ---- S = Q K^T ----
#pragma unroll
            for (int kc = 0; kc < 4; kc++) {
                uint32_t k4[4][4];
#pragma unroll
                for (int np = 0; np < 4; np++)
                    ldsm4(k4[np], sK + boff + (uint32_t)(np * 16 * P144) + kc * 32);
#pragma unroll
                for (int np = 0; np < 4; np++) {
                    mma_f16(S[2*np],   qh[kc], k4[np]);
                    mma_f16(S[2*np+1], qh[kc], k4[np] + 2);
                }
            }

            const int row0 = q0 + wr0 + g;
            const int row1 = row0 + 8;
            float mx0 = -1e30f, mx1 = -1e30f;
            if (kt * 64 + 63 <= q0 + wr0) {
#pragma unroll
                for (int nt = 0; nt < 8; nt++) {
                    mx0 = fmaxf(mx0, fmaxf(S[nt][0], S[nt][1]));
                    mx1 = fmaxf(mx1, fmaxf(S[nt][2], S[nt][3]));
                }
            } else {
                const int kb = kt * 64 + t4 * 2;
#pragma unroll
                for (int nt = 0; nt < 8; nt++) {
                    const int k0 = kb + nt * 8;
                    S[nt][0] = (k0     <= row0) ? S[nt][0] : -1e30f;
                    S[nt][1] = (k0 + 1 <= row0) ? S[nt][1] : -1e30f;
                    S[nt][2] = (k0     <= row1) ? S[nt][2] : -1e30f;
                    S[nt][3] = (k0 + 1 <= row1) ? S[nt][3] : -1e30f;
                    mx0 = fmaxf(mx0, fmaxf(S[nt][0], S[nt][1]));
                    mx1 = fmaxf(mx1, fmaxf(S[nt][2], S[nt][3]));
                }
            }
            mx0 = fmaxf(mx0, __shfl_xor_sync(0xffffffffu, mx0, 1));
            mx0 = fmaxf(mx0, __shfl_xor_sync(0xffffffffu, mx0, 2));
            mx1 = fmaxf(mx1, __shfl_xor_sync(0xffffffffu, mx1, 1));
            mx1 = fmaxf(mx1, __shfl_xor_sync(0xffffffffu, mx1, 2));

            const float mn0 = fmaxf(m0, mx0);
            const float mn1 = fmaxf(m1, mx1);
            const float a0  = ex2(m0 - mn0);
            const float a1  = ex2(m1 - mn1);
            float rs0 = 0.0f, rs1 = 0.0f;
#pragma unroll
            for (int nt = 0; nt < 8; nt++) {
                S[nt][0] = ex2(S[nt][0] - mn0);
                S[nt][1] = ex2(S[nt][1] - mn0);
                S[nt][2] = ex2(S[nt][2] - mn1);
                S[nt][3] = ex2(S[nt][3] - mn1);
                rs0 += S[nt][0] + S[nt][1];
                rs1 += S[nt][2] + S[nt][3];
            }
            rs0 += __shfl_xor_sync(0xffffffffu, rs0, 1);
            rs0 += __shfl_xor_sync(0xffffffffu, rs0, 2);
            rs1 += __shfl_xor_sync(0xffffffffu, rs1, 1);
            rs1 += __shfl_xor_sync(0xffffffffu, rs1, 2);
            l0 = l0 * a0 + rs0;  m0 = mn0;
            l1 = l1 * a1 + rs1;  m1 = mn1;
#pragma unroll
            for (int d = 0; d < 8; d++) {
                O[d][0] *= a0; O[d][1] *= a0;
                O[d][2] *= a1; O[d][3] *= a1;
            }

            // ---- P -> fp16 A-fragments ----
            uint32_t Ph[4][4];
#pragma unroll
            for (int kc2 = 0; kc2 < 4; kc2++) {
#pragma unroll
                for (int part = 0; part < 2; part++) {
                    const int nt = 2 * kc2 + part;
#pragma unroll
                    for (int pr = 0; pr < 2; pr++) {
                        const __half2 hh = __halves2half2(
                            __float2half_rn(S[nt][2*pr + 0]),
                            __float2half_rn(S[nt][2*pr + 1]));
                        Ph[kc2][part*2 + pr] = *(const uint32_t*)&hh;
                    }
                }
            }

            // ---- O += P V ----
#pragma unroll
            for (int kc2 = 0; kc2 < 4; kc2++) {
                const uint32_t vrow = (uint32_t)((kc2 * 16 + (mid & 1) * 8 + lr) * P144);
                uint32_t v4[4][4];
#pragma unroll
                for (int dtp = 0; dtp < 4; dtp++)
                    ldsm4t(v4[dtp], sV + vrow + (uint32_t)(dtp * 32) + (mid >> 1) * 16);
#pragma unroll
                for (int dtp = 0; dtp < 4; dtp++) {
                    mma_f16(O[2*dtp],   Ph[kc2], v4[dtp]);
                    mma_f16(O[2*dtp+1], Ph[kc2], v4[dtp] + 2);
                }
            }
        }
        __syncthreads();
    }

    const float i0 = 1.0f / l0;
    const float i1 = 1.0f / l1;
    const int row0 = q0 + wr0 + g;
    const int colb = h * DK + t4 * 2;
#pragma unroll
    for (int dt = 0; dt < 8; dt++) {
        const int col = colb + dt * 8;
        {
            const size_t idx = ((size_t)b * SS + row0) * DDm + col;
            *(__half2*)(Ch + idx) = __halves2half2(
                __float2half_rn(O[dt][0] * i0),
                __float2half_rn(O[dt][1] * i0));
        }
        {
            const size_t idx = ((size_t)b * SS + row0 + 8) * DDm + col;
            *(__half2*)(Ch + idx) = __halves2half2(
                __float2half_rn(O[dt][2] * i1),
                __float2half_rn(O[dt][3] * i1));
        }
    }
}

// ---------------------------------------------------------------------------
extern "C" void kernel_launch(void* const* d_in, const int* in_sizes, int n_in,
                              void* d_out, int out_size)
{
    const float* q  = (const float*)d_in[0];
    const float* k  = (const float*)d_in[1];
    const float* v  = (const float*)d_in[2];
    // d_in[3] = causal mask (structure applied analytically)
    const float* wq = (const float*)d_in[4];
    const float* bq = (const float*)d_in[5];
    const float* wk = (const float*)d_in[6];
    const float* bk = (const float*)d_in[7];
    const float* wv = (const float*)d_in[8];
    const float* bv = (const float*)d_in[9];
    const float* wo = (const float*)d_in[10];
    const float* bo = (const float*)d_in[11];
    float* out = (float*)d_out;

    __half *gQh, *gKh, *gVh, *gAh;
    __half *gXqh, *gXkh, *gXvh;
    __half *gWqh, *gWkh, *gWvh, *gWoh;
    cudaGetSymbolAddress((void**)&gQh, g_Qh);
    cudaGetSymbolAddress((void**)&gKh, g_Kh);
    cudaGetSymbolAddress((void**)&gVh, g_Vh);
    cudaGetSymbolAddress((void**)&gAh, g_Ah);
    cudaGetSymbolAddress((void**)&gXqh, g_Xqh);
    cudaGetSymbolAddress((void**)&gXkh, g_Xkh);
    cudaGetSymbolAddress((void**)&gXvh, g_Xvh);
    cudaGetSymbolAddress((void**)&gWqh, g_Wqh);
    cudaGetSymbolAddress((void**)&gWkh, g_Wkh);
    cudaGetSymbolAddress((void**)&gWvh, g_Wvh);
    cudaGetSymbolAddress((void**)&gWoh, g_Woh);

    cudaFuncSetAttribute(gemm_qkv, cudaFuncAttributeMaxDynamicSharedMemorySize, GEMM_SMEM);
    cudaFuncSetAttribute(gemm_o,   cudaFuncAttributeMaxDynamicSharedMemorySize, GEMM_SMEM);
    cudaFuncSetAttribute(attn_mma, cudaFuncAttributeMaxDynamicSharedMemorySize, ATT_SMEM);

    const float cs = 0.125f * 1.4426950408889634f;   // 1/sqrt(DK) * log2(e)

    // 1) ONE fused conversion launch: 4 weights + 3 inputs
    {
        const int n4w = DDm * DDm / 4;              // 262144
        const int bpw = (n4w + 255) / 256;          // 1024
        const int n4a = MT * DDm / 4;               // 1048576
        const int bpa = (n4a + 255) / 256;          // 4096
        split_all<<<4 * bpw + 3 * bpa, 256>>>(
            (const float4*)wq, (const float4*)wk, (const float4*)wv, (const float4*)wo,
            (const float4*)q,  (const float4*)k,  (const float4*)v,
            (__half2*)gWqh, (__half2*)gWkh, (__half2*)gWvh, (__half2*)gWoh,
            (__half2*)gXqh, (__half2*)gXkh, (__half2*)gXvh,
            n4w, bpw, n4a, bpa);
    }

    // 2) fused Q/K/V projections: 1-warp 64x64 CTAs, grid (16, 64, 3)
    {
        const dim3 gg(DDm / 64, MT / 64, 3);
        gemm_qkv<<<gg, 32, GEMM_SMEM>>>(
            gXqh, gXkh, gXvh,
            gWqh, gWkh, gWvh,
            bq, bk, bv,
            gQh, gKh, gVh,
            cs, MT, DDm, DDm);
    }

    // 3) attention -> ctx in gAh
    attn_mma<<<dim3(SS / 128, HH, BB), 256, ATT_SMEM>>>(gQh, gKh, gVh, gAh);

    // 4) output projection: 1-warp 64x64 CTAs, grid (16, 64)
    gemm_o<<<dim3(DDm / 64, MT / 64), 32, GEMM_SMEM>>>(
        gAh, gWoh, bo, out, MT, DDm, DDm);
}

// round 15
// speedup vs baseline: 1.1137x; 1.1137x over previous
#include <cuda_runtime.h>
#include <cuda_fp16.h>
#include <cstdint>

// Problem constants
#define BB  2
#define SS  2048
#define DDm 1024
#define HH  16
#define DK  64
#define MT  (BB*SS)      // 4096

// Scratch (allocation-free: __device__ globals), all fp16
__device__ __half g_Qh[BB*HH*SS*DK];
__device__ __half g_Kh[BB*HH*SS*DK];
__device__ __half g_Vh[BB*HH*SS*DK];
__device__ __half g_Ah[MT*DDm];        // attn ctx (O-proj input)
__device__ __half g_Wqh[DDm*DDm];
__device__ __half g_Wkh[DDm*DDm];
__device__ __half g_Wvh[DDm*DDm];
__device__ __half g_Woh[DDm*DDm];

// ---------------------------------------------------------------------------
// helpers
// ---------------------------------------------------------------------------
__device__ __forceinline__ uint32_t smem_u32(const void* p) {
    uint32_t a;
    asm("{ .reg .u64 t; cvta.to.shared.u64 t, %1; cvt.u32.u64 %0, t; }"
        : "=r"(a) : "l"(p));
    return a;
}
__device__ __forceinline__ void cp16(uint32_t saddr, const void* gaddr) {
    asm volatile("cp.async.cg.shared.global [%0], [%1], 16;"
                 :: "r"(saddr), "l"(gaddr));
}
__device__ __forceinline__ void ldsm4(uint32_t* r, uint32_t addr) {
    asm volatile("ldmatrix.sync.aligned.m8n8.x4.shared.b16 {%0,%1,%2,%3}, [%4];"
                 : "=r"(r[0]), "=r"(r[1]), "=r"(r[2]), "=r"(r[3]) : "r"(addr));
}
__device__ __forceinline__ void ldsm4t(uint32_t* r, uint32_t addr) {
    asm volatile("ldmatrix.sync.aligned.m8n8.x4.trans.shared.b16 {%0,%1,%2,%3}, [%4];"
                 : "=r"(r[0]), "=r"(r[1]), "=r"(r[2]), "=r"(r[3]) : "r"(addr));
}
__device__ __forceinline__ void mma_f16(float* c, const uint32_t* a,
                                        const uint32_t* b) {
    asm volatile(
        "mma.sync.aligned.m16n8k16.row.col.f32.f16.f16.f32 "
        "{%0,%1,%2,%3}, {%4,%5,%6,%7}, {%8,%9}, {%0,%1,%2,%3};"
        : "+f"(c[0]), "+f"(c[1]), "+f"(c[2]), "+f"(c[3])
        : "r"(a[0]), "r"(a[1]), "r"(a[2]), "r"(a[3]), "r"(b[0]), "r"(b[1]));
}
__device__ __forceinline__ float ex2(float x) {
    float r;
    asm("ex2.approx.f32 %0, %1;" : "=f"(r) : "f"(x));
    return r;
}

// ---------------------------------------------------------------------------
// fused fp32 -> fp16 convert: 4 weight tensors in ONE launch
// ---------------------------------------------------------------------------
__global__ void __launch_bounds__(256) split_w(
    const float4* __restrict__ x0, const float4* __restrict__ x1,
    const float4* __restrict__ x2, const float4* __restrict__ x3,
    __half2* __restrict__ h0, __half2* __restrict__ h1,
    __half2* __restrict__ h2, __half2* __restrict__ h3,
    int n4each, int blocksPer)
{
    const int seg = blockIdx.x / blocksPer;
    const int bid = blockIdx.x % blocksPer;
    const float4* x = (seg == 0) ? x0 : (seg == 1) ? x1 : (seg == 2) ? x2 : x3;
    __half2* hi = (seg == 0) ? h0 : (seg == 1) ? h1 : (seg == 2) ? h2 : h3;

    const int i = bid * blockDim.x + threadIdx.x;
    if (i >= n4each) return;
    float4 v = x[i];
    hi[2*i]   = __halves2half2(__float2half_rn(v.x), __float2half_rn(v.y));
    hi[2*i+1] = __halves2half2(__float2half_rn(v.z), __float2half_rn(v.w));
}

// ---------------------------------------------------------------------------
// GEMM tiles: CTA 128x128, 128 threads (4 warps, 64x64 warp tile), BK=32,
// 2-stage double buffer, row pitch 80 B.
// ---------------------------------------------------------------------------
#define TILE_B   10240              // 128 rows * 80 B
#define STAGE_B  (2 * TILE_B)       // A16, W
#define GEMM_SMEM (2 * STAGE_B)     // 40960

// fused Q/K/V projection, A read as fp32 with inline convert.
// blockIdx.z selects (input, weight, bias, output).
__global__ void __launch_bounds__(128) gemm_qkv(
    const float* __restrict__ Aq, const float* __restrict__ Ak,
    const float* __restrict__ Av,
    const __half* __restrict__ Wq, const __half* __restrict__ Wk,
    const __half* __restrict__ Wv,
    const float* __restrict__ bq, const float* __restrict__ bk,
    const float* __restrict__ bv,
    __half* __restrict__ Cq, __half* __restrict__ Ck, __half* __restrict__ Cv,
    float csq, int M, int N, int K)
{
    extern __shared__ __align__(16) char smem[];
    const uint32_t sbase = smem_u32(smem);

    const int z = blockIdx.z;
    const float*  A = (z == 0) ? Aq : (z == 1) ? Ak : Av;
    const __half* W = (z == 0) ? Wq : (z == 1) ? Wk : Wv;
    const float*  bias = (z == 0) ? bq : (z == 1) ? bk : bv;
    __half*       Ch = (z == 0) ? Cq : (z == 1) ? Ck : Cv;
    const float   oscale = (z == 0) ? csq : 1.0f;

    const int tid  = threadIdx.x;
    const int lane = tid & 31;
    const int wid  = tid >> 5;
    const int wr   = wid >> 1;
    const int wc   = wid & 1;
    const int m0   = blockIdx.y * 128;
    const int n0   = blockIdx.x * 128;

    float acc[4][8][4];
#pragma unroll
    for (int i = 0; i < 4; i++)
#pragma unroll
        for (int j = 0; j < 8; j++)
#pragma unroll
            for (int r = 0; r < 4; r++) acc[i][j][r] = 0.0f;

    // A fp32 prefetch registers: 8 float4 per thread = one 128x32 tile
    float4 a4[8];
    auto ldg_A = [&](int i) {
        const int kc0 = i * 32;
#pragma unroll
        for (int h = 0; h < 8; h++) {
            const int idx = tid + h * 128;
            const int row = idx >> 3, c4 = idx & 7;
            a4[h] = *(const float4*)(A + (size_t)(m0 + row) * K + kc0 + c4 * 4);
        }
    };
    // convert regs -> fp16 smem A tile (row pitch 80)
    auto sts_A = [&](int buf) {
        char* stage = smem + buf * STAGE_B;
#pragma unroll
        for (int h = 0; h < 8; h++) {
            const int idx = tid + h * 128;
            const int row = idx >> 3, c4 = idx & 7;
            const __half2 p0 = __float22half2_rn(make_float2(a4[h].x, a4[h].y));
            const __half2 p1 = __float22half2_rn(make_float2(a4[h].z, a4[h].w));
            uint2 u;
            u.x = *(const uint32_t*)&p0;
            u.y = *(const uint32_t*)&p1;
            *(uint2*)(stage + row * 80 + c4 * 8) = u;
        }
    };
    // W fp16 cp.async (tile at stage + TILE_B)
    auto cp_W = [&](int i, int buf) {
        const int kc0 = i * 32;
        const uint32_t stage = sbase + (uint32_t)buf * STAGE_B + TILE_B;
#pragma unroll
        for (int h = 0; h < 4; h++) {
            const int idx = tid + h * 128;
            const int row = idx >> 2, c = idx & 3;
            cp16(stage + row * 80 + c * 16,
                 W + (size_t)(n0 + row) * K + kc0 + c * 8);
        }
    };

    const int mid = lane >> 3;
    const int lr  = lane & 7;
    const int a_moff = (mid & 1) * 8;
    const int a_koff = (mid >> 1) * 8;
    const int b_noff = (mid >> 1) * 8;
    const int b_koff = (mid & 1) * 8;

    const int NCH = K / 32;   // 32

    ldg_A(0);
    cp_W(0, 0);
    asm volatile("cp.async.commit_group;" ::: "memory");

    for (int i = 0; i < NCH; i++) {
        const int buf = i & 1;
        sts_A(buf);                        // A16[buf] from regs (chunk i)
        if (i + 1 < NCH) {
            cp_W(i + 1, buf ^ 1);
            asm volatile("cp.async.commit_group;" ::: "memory");
            asm volatile("cp.async.wait_group 1;" ::: "memory");   // W[i] done
        } else {
            asm volatile("cp.async.wait_group 0;" ::: "memory");
        }
        __syncthreads();                   // A16[buf] + W[buf] visible

        if (i + 1 < NCH) ldg_A(i + 1);     // prefetch next A into regs

        const uint32_t stage = sbase + (uint32_t)buf * STAGE_B;
        const uint32_t tAh = stage;
        const uint32_t tWh = stage + TILE_B;

#pragma unroll
        for (int ks = 0; ks < 2; ks++) {
            uint32_t ah[4][4], bh[8][2];
#pragma unroll
            for (int mt = 0; mt < 4; mt++) {
                const int r  = wr * 64 + mt * 16 + a_moff + lr;
                const int kc = ks * 16 + a_koff;
                ldsm4(ah[mt], tAh + r * 80 + kc * 2);
            }
#pragma unroll
            for (int np = 0; np < 4; np++) {
                const int r  = wc * 64 + np * 16 + b_noff + lr;
                const int kc = ks * 16 + b_koff;
                uint32_t t4r[4];
                ldsm4(t4r, tWh + r * 80 + kc * 2);
                bh[2*np][0] = t4r[0]; bh[2*np][1] = t4r[1];
                bh[2*np+1][0] = t4r[2]; bh[2*np+1][1] = t4r[3];
            }
#pragma unroll
            for (int mt = 0; mt < 4; mt++)
#pragma unroll
                for (int nt = 0; nt < 8; nt++)
                    mma_f16(acc[mt][nt], ah[mt], bh[nt]);
        }
        __syncthreads();
    }

    const int g  = lane >> 2;
    const int t4 = lane & 3;
#pragma unroll
    for (int mt = 0; mt < 4; mt++) {
#pragma unroll
        for (int nt = 0; nt < 8; nt++) {
            const int col = n0 + wc * 64 + nt * 8 + t4 * 2;
            const float bx = bias[col], by = bias[col + 1];
#pragma unroll
            for (int half = 0; half < 2; half++) {
                const int row = m0 + wr * 64 + mt * 16 + g + half * 8;
                const float v0 = (acc[mt][nt][half * 2 + 0] + bx) * oscale;
                const float v1 = (acc[mt][nt][half * 2 + 1] + by) * oscale;
                const int bi = row >> 11;
                const int s  = row & (SS - 1);
                const int h  = col >> 6;
                const int dk = col & 63;
                const size_t idx = (((size_t)(bi * HH + h) * SS + s) * DK + dk);
                *(__half2*)(Ch + idx) = __halves2half2(
                    __float2half_rn(v0), __float2half_rn(v1));
            }
        }
    }
}

// O projection: fp16 A (ctx) via cp.async, fp32 output. (R13 body.)
__global__ void __launch_bounds__(128) gemm_o(
    const __half* __restrict__ Ah, const __half* __restrict__ Wh,
    const float* __restrict__ bias, float* __restrict__ C,
    int M, int N, int K)
{
    extern __shared__ __align__(16) char smem[];
    const uint32_t sbase = smem_u32(smem);

    const int tid  = threadIdx.x;
    const int lane = tid & 31;
    const int wid  = tid >> 5;
    const int wr   = wid >> 1;
    const int wc   = wid & 1;
    const int m0   = blockIdx.y * 128;
    const int n0   = blockIdx.x * 128;

    float acc[4][8][4];
#pragma unroll
    for (int i = 0; i < 4; i++)
#pragma unroll
        for (int j = 0; j < 8; j++)
#pragma unroll
            for (int r = 0; r < 4; r++) acc[i][j][r] = 0.0f;

    auto load_chunk = [&](int i, int buf) {
        const int kc0 = i * 32;
        const uint32_t stage = sbase + (uint32_t)buf * STAGE_B;
#pragma unroll
        for (int t = 0; t < 2; t++) {
            const __half* src = (t == 0) ? Ah : Wh;
            const int r0 = (t == 0) ? m0 : n0;
#pragma unroll
            for (int h = 0; h < 4; h++) {
                const int idx = tid + h * 128;
                const int row = idx >> 2, c = idx & 3;
                cp16(stage + t * TILE_B + row * 80 + c * 16,
                     src + (size_t)(r0 + row) * K + kc0 + c * 8);
            }
        }
    };

    const int mid = lane >> 3;
    const int lr  = lane & 7;
    const int a_moff = (mid & 1) * 8;
    const int a_koff = (mid >> 1) * 8;
    const int b_noff = (mid >> 1) * 8;
    const int b_koff = (mid & 1) * 8;

    const int NCH = K / 32;

    load_chunk(0, 0);
    asm volatile("cp.async.commit_group;" ::: "memory");

    for (int i = 0; i < NCH; i++) {
        if (i + 1 < NCH) {
            load_chunk(i + 1, (i + 1) & 1);
            asm volatile("cp.async.commit_group;" ::: "memory");
            asm volatile("cp.async.wait_group 1;" ::: "memory");
        } else {
            asm volatile("cp.async.wait_group 0;" ::: "memory");
        }
        __syncthreads();

        const uint32_t stage = sbase + (uint32_t)(i & 1) * STAGE_B;
        const uint32_t tAh = stage;
        const uint32_t tWh = stage + TILE_B;

#pragma unroll
        for (int ks = 0; ks < 2; ks++) {
            uint32_t ah[4][4], bh[8][2];
#pragma unroll
            for (int mt = 0; mt < 4; mt++) {
                const int r  = wr * 64 + mt * 16 + a_moff + lr;
                const int kc = ks * 16 + a_koff;
                ldsm4(ah[mt], tAh + r * 80 + kc * 2);
            }
#pragma unroll
            for (int np = 0; np < 4; np++) {
                const int r  = wc * 64 + np * 16 + b_noff + lr;
                const int kc = ks * 16 + b_koff;
                uint32_t t4r[4];
                ldsm4(t4r, tWh + r * 80 + kc * 2);
                bh[2*np][0] = t4r[0]; bh[2*np][1] = t4r[1];
                bh[2*np+1][0] = t4r[2]; bh[2*np+1][1] = t4r[3];
            }
#pragma unroll
            for (int mt = 0; mt < 4; mt++)
#pragma unroll
                for (int nt = 0; nt < 8; nt++)
                    mma_f16(acc[mt][nt], ah[mt], bh[nt]);
        }
        __syncthreads();
    }

    const int g  = lane >> 2;
    const int t4 = lane & 3;
#pragma unroll
    for (int mt = 0; mt < 4; mt++) {
#pragma unroll
        for (int nt = 0; nt < 8; nt++) {
            const int col = n0 + wc * 64 + nt * 8 + t4 * 2;
            const float bx = bias[col], by = bias[col + 1];
#pragma unroll
            for (int half = 0; half < 2; half++) {
                const int row = m0 + wr * 64 + mt * 16 + g + half * 8;
                const float v0 = acc[mt][nt][half * 2 + 0] + bx;
                const float v1 = acc[mt][nt][half * 2 + 1] + by;
                float* dst = C + (size_t)row * N + col;
                *(float2*)dst = make_float2(v0, v1);
            }
        }
    }
}

// ---------------------------------------------------------------------------
// Flash attention via fp16 HMMA, all single-product (unchanged from R13).
// ---------------------------------------------------------------------------
#define P144 144
#define KV_T   (64 * P144)
#define KV_ST  (2 * KV_T)
#define Q_BYTES (128 * P144)
#define ATT_SMEM (Q_BYTES + 2 * KV_ST)   // 55296

__global__ void __launch_bounds__(256) attn_mma(
    const __half* __restrict__ Q_, const __half* __restrict__ K_,
    const __half* __restrict__ V_, __half* __restrict__ Ch)
{
    extern __shared__ __align__(16) char smem[];
    const uint32_t sb = smem_u32(smem);

    const int qt = (int)gridDim.x - 1 - (int)blockIdx.x;
    const int h = blockIdx.y, b = blockIdx.z;
    const int q0 = qt * 128;
    const size_t bh = ((size_t)b * HH + h) * SS * DK;

    const int tid  = threadIdx.x;
    const int lane = tid & 31;
    const int wid  = tid >> 5;
    const int wr0  = wid * 16;
    const int g    = lane >> 2;
    const int t4   = lane & 3;
    const int mid  = lane >> 3;
    const int lr   = lane & 7;

    const int nkt = 2 * (qt + 1);

    auto load_kv = [&](int kt, int buf) {
        const uint32_t stage = sb + Q_BYTES + (uint32_t)buf * KV_ST;
        const size_t go = bh + (size_t)kt * 64 * DK;
        const __half* srcs[2] = {K_ + go, V_ + go};
#pragma unroll
        for (int t = 0; t < 2; t++) {
#pragma unroll
            for (int j = 0; j < 2; j++) {
                const int idx = tid + j * 256;
                const int r = idx >> 3, s = idx & 7;
                cp16(stage + t * KV_T + r * P144 + s * 16, srcs[t] + r * 64 + s * 8);
            }
        }
    };

    load_kv(0, 0);
    asm volatile("cp.async.commit_group;" ::: "memory");

    {
        const __half* sq = Q_ + bh + (size_t)q0 * DK;
#pragma unroll
        for (int j = 0; j < 4; j++) {
            const int idx = tid + j * 256;
            const int r = idx >> 3, s = idx & 7;
            *(uint4*)(smem + r * P144 + s * 16) = *(const uint4*)(sq + r * 64 + s * 8);
        }
    }
    __syncthreads();

    const uint32_t aoff = (uint32_t)((wr0 + (mid & 1) * 8 + lr) * P144) + (mid >> 1) * 16;
    uint32_t qh[4][4];
#pragma unroll
    for (int kc = 0; kc < 4; kc++)
        ldsm4(qh[kc], sb + aoff + kc * 32);

    float m0 = -1e30f, m1 = -1e30f, l0 = 0.0f, l1 = 0.0f;
    float O[8][4];
#pragma unroll
    for (int d = 0; d < 8; d++)
#pragma unroll
        for (int e = 0; e < 4; e++) O[d][e] = 0.0f;

    const uint32_t boff = (uint32_t)(((mid >> 1) * 8 + lr) * P144) + (mid & 1) * 16;

    for (int kt = 0; kt < nkt; kt++) {
        if (kt + 1 < nkt) {
            load_kv(kt + 1, (kt + 1) & 1);
            asm volatile("cp.async.commit_group;" ::: "memory");
            asm volatile("cp.async.wait_group 1;" ::: "memory");
        } else {
            asm volatile("cp.async.wait_group 0;" ::: "memory");
        }
        __syncthreads();

        if (kt * 64 <= q0 + wr0 + 15) {
            const uint32_t stage = sb + Q_BYTES + (uint32_t)(kt & 1) * KV_ST;
            const uint32_t sK = stage, sV = stage + KV_T;

            float S[8][4];
#pragma unroll
            for (int nt = 0; nt < 8; nt++)
#pragma unroll
                for (int e = 0; e < 4; e++) S[nt][e] = 0.0f;

#pragma unroll
            for (int kc = 0; kc < 4; kc++) {
                uint32_t k4[4][4];
#pragma unroll
                for (int np = 0; np < 4; np++)
                    ldsm4(k4[np], sK + boff + (uint32_t)(np * 16 * P144) + kc * 32);
#pragma unroll
                for (int np = 0; np < 4; np++) {
                    mma_f16(S[2*np],   qh[kc], k4[np]);
                    mma_f16(S[2*np+1], qh[kc], k4[np] + 2);
                }
            }

            const int row0 = q0 + wr0 + g;
            const int row1 = row0 + 8;
            float mx0 = -1e30f, mx1 = -1e30f;
            if (kt * 64 + 63 <= q0 + wr0) {
#pragma unroll
                for (int nt = 0; nt < 8; nt++) {
                    mx0 = fmaxf(mx0, fmaxf(S[nt][0], S[nt][1]));
                    mx1 = fmaxf(mx1, fmaxf(S[nt][2], S[nt][3]));
                }
            } else {
                const int kb = kt * 64 + t4 * 2;
#pragma unroll
                for (int nt = 0; nt < 8; nt++) {
                    const int k0 = kb + nt * 8;
                    S[nt][0] = (k0     <= row0) ? S[nt][0] : -1e30f;
                    S[nt][1] = (k0 + 1 <= row0) ? S[nt][1] : -1e30f;
                    S[nt][2] = (k0     <= row1) ? S[nt][2] : -1e30f;
                    S[nt][3] = (k0 + 1 <= row1) ? S[nt][3] : -1e30f;
                    mx0 = fmaxf(mx0, fmaxf(S[nt][0], S[nt][1]));
                    mx1 = fmaxf(mx1, fmaxf(S[nt][2], S[nt][3]));
                }
            }
            mx0 = fmaxf(mx0, __shfl_xor_sync(0xffffffffu, mx0, 1));
            mx0 = fmaxf(mx0, __shfl_xor_sync(0xffffffffu, mx0, 2));
            mx1 = fmaxf(mx1, __shfl_xor_sync(0xffffffffu, mx1, 1));
            mx1 = fmaxf(mx1, __shfl_xor_sync(0xffffffffu, mx1, 2));

            const float mn0 = fmaxf(m0, mx0);
            const float mn1 = fmaxf(m1, mx1);
            const float a0  = ex2(m0 - mn0);
            const float a1  = ex2(m1 - mn1);
            float rs0 = 0.0f, rs1 = 0.0f;
#pragma unroll
            for (int nt = 0; nt < 8; nt++) {
                S[nt][0] = ex2(S[nt][0] - mn0);
                S[nt][1] = ex2(S[nt][1] - mn0);
                S[nt][2] = ex2(S[nt][2] - mn1);
                S[nt][3] = ex2(S[nt][3] - mn1);
                rs0 += S[nt][0] + S[nt][1];
                rs1 += S[nt][2] + S[nt][3];
            }
            rs0 += __shfl_xor_sync(0xffffffffu, rs0, 1);
            rs0 += __shfl_xor_sync(0xffffffffu, rs0, 2);
            rs1 += __shfl_xor_sync(0xffffffffu, rs1, 1);
            rs1 += __shfl_xor_sync(0xffffffffu, rs1, 2);
            l0 = l0 * a0 + rs0;  m0 = mn0;
            l1 = l1 * a1 + rs1;  m1 = mn1;
#pragma unroll
            for (int d = 0; d < 8; d++) {
                O[d][0] *= a0; O[d][1] *= a0;
                O[d][2] *= a1; O[d][3] *= a1;
            }

            uint32_t Ph[4][4];
#pragma unroll
            for (int kc2 = 0; kc2 < 4; kc2++) {
#pragma unroll
                for (int part = 0; part < 2; part++) {
                    const int nt = 2 * kc2 + part;
#pragma unroll
                    for (int pr = 0; pr < 2; pr++) {
                        const __half2 hh = __halves2half2(
                            __float2half_rn(S[nt][2*pr + 0]),
                            __float2half_rn(S[nt][2*pr + 1]));
                        Ph[kc2][part*2 + pr] = *(const uint32_t*)&hh;
                    }
                }
            }

#pragma unroll
            for (int kc2 = 0; kc2 < 4; kc2++) {
                const uint32_t vrow = (uint32_t)((kc2 * 16 + (mid & 1) * 8 + lr) * P144);
                uint32_t v4[4][4];
#pragma unroll
                for (int dtp = 0; dtp < 4; dtp++)
                    ldsm4t(v4[dtp], sV + vrow + (uint32_t)(dtp * 32) + (mid >> 1) * 16);
#pragma unroll
                for (int dtp = 0; dtp < 4; dtp++) {
                    mma_f16(O[2*dtp],   Ph[kc2], v4[dtp]);
                    mma_f16(O[2*dtp+1], Ph[kc2], v4[dtp] + 2);
                }
            }
        }
        __syncthreads();
    }

    const float i0 = 1.0f / l0;
    const float i1 = 1.0f / l1;
    const int row0 = q0 + wr0 + g;
    const int colb = h * DK + t4 * 2;
#pragma unroll
    for (int dt = 0; dt < 8; dt++) {
        const int col = colb + dt * 8;
        {
            const size_t idx = ((size_t)b * SS + row0) * DDm + col;
            *(__half2*)(Ch + idx) = __halves2half2(
                __float2half_rn(O[dt][0] * i0),
                __float2half_rn(O[dt][1] * i0));
        }
        {
            const size_t idx = ((size_t)b * SS + row0 + 8) * DDm + col;
            *(__half2*)(Ch + idx) = __halves2half2(
                __float2half_rn(O[dt][2] * i1),
                __float2half_rn(O[dt][3] * i1));
        }
    }
}

// ---------------------------------------------------------------------------
extern "C" void kernel_launch(void* const* d_in, const int* in_sizes, int n_in,
                              void* d_out, int out_size)
{
    const float* q  = (const float*)d_in[0];
    const float* k  = (const float*)d_in[1];
    const float* v  = (const float*)d_in[2];
    // d_in[3] = causal mask (structure applied analytically)
    const float* wq = (const float*)d_in[4];
    const float* bq = (const float*)d_in[5];
    const float* wk = (const float*)d_in[6];
    const float* bk = (const float*)d_in[7];
    const float* wv = (const float*)d_in[8];
    const float* bv = (const float*)d_in[9];
    const float* wo = (const float*)d_in[10];
    const float* bo = (const float*)d_in[11];
    float* out = (float*)d_out;

    __half *gQh, *gKh, *gVh, *gAh;
    __half *gWqh, *gWkh, *gWvh, *gWoh;
    cudaGetSymbolAddress((void**)&gQh, g_Qh);
    cudaGetSymbolAddress((void**)&gKh, g_Kh);
    cudaGetSymbolAddress((void**)&gVh, g_Vh);
    cudaGetSymbolAddress((void**)&gAh, g_Ah);
    cudaGetSymbolAddress((void**)&gWqh, g_Wqh);
    cudaGetSymbolAddress((void**)&gWkh, g_Wkh);
    cudaGetSymbolAddress((void**)&gWvh, g_Wvh);
    cudaGetSymbolAddress((void**)&gWoh, g_Woh);

    cudaFuncSetAttribute(gemm_qkv, cudaFuncAttributeMaxDynamicSharedMemorySize, GEMM_SMEM);
    cudaFuncSetAttribute(gemm_o,   cudaFuncAttributeMaxDynamicSharedMemorySize, GEMM_SMEM);
    cudaFuncSetAttribute(attn_mma, cudaFuncAttributeMaxDynamicSharedMemorySize, ATT_SMEM);

    const float cs = 0.125f * 1.4426950408889634f;   // 1/sqrt(DK) * log2(e)

    // 1) weights-only conversion (inputs converted inline in gemm_qkv)
    {
        const int n4w = DDm * DDm / 4;
        const int bpw = (n4w + 255) / 256;
        split_w<<<4 * bpw, 256>>>(
            (const float4*)wq, (const float4*)wk, (const float4*)wv, (const float4*)wo,
            (__half2*)gWqh, (__half2*)gWkh, (__half2*)gWvh, (__half2*)gWoh,
            n4w, bpw);
    }

    // 2) fused Q/K/V projections, fp32 A inline-converted (grid.z = 3)
    {
        const dim3 gg(DDm / 128, MT / 128, 3);
        gemm_qkv<<<gg, 128, GEMM_SMEM>>>(
            q, k, v,
            gWqh, gWkh, gWvh,
            bq, bk, bv,
            gQh, gKh, gVh,
            cs, MT, DDm, DDm);
    }

    // 3) attention -> ctx in gAh
    attn_mma<<<dim3(SS / 128, HH, BB), 256, ATT_SMEM>>>(gQh, gKh, gVh, gAh);

    // 4) output projection
    gemm_o<<<dim3(DDm / 128, MT / 128), 128, GEMM_SMEM>>>(
        gAh, gWoh, bo, out, MT, DDm, DDm);
}